// round 3
// baseline (speedup 1.0000x reference)
#include <cuda_runtime.h>

#define Bsz 4
#define Tn 2048
#define Cn 1024
#define Hn 16
#define Dn 64
#define NTOK (Bsz*Tn)   // 8192

// Scratch (device globals: allocation-free)
__device__ float g_q[Bsz*Hn*Tn*Dn];
__device__ float g_k[Bsz*Hn*Tn*Dn];
__device__ float g_v[Bsz*Hn*Tn*Dn];
__device__ float g_y[Bsz*Tn*Cn];

// ---------------------------------------------------------------------------
// GEMM1: qkv = x[8192,1024] @ W_attn[1024,3072] + b_attn
// scatter into g_q/g_k/g_v with layout [B,H,T,D]; q scaled by 1/sqrt(D)
// 128x128 block tile, K-step 8, 256 threads, 8x8 per thread.
// ---------------------------------------------------------------------------
__global__ __launch_bounds__(256) void gemm_qkv_kernel(
    const float* __restrict__ X, const float* __restrict__ W,
    const float* __restrict__ bias)
{
    __shared__ float As[8][128];
    __shared__ float Bs[8][128];
    const int tid = threadIdx.x;
    const int tx = tid & 15, ty = tid >> 4;
    const int m0 = blockIdx.y * 128;
    const int n0 = blockIdx.x * 128;

    const int arow = tid >> 1, akq = (tid & 1) * 4;
    const int bk = tid >> 5, bnq = (tid & 31) * 4;

    float acc[8][8];
#pragma unroll
    for (int i = 0; i < 8; i++)
#pragma unroll
        for (int j = 0; j < 8; j++) acc[i][j] = 0.0f;

    for (int k0 = 0; k0 < 1024; k0 += 8) {
        __syncthreads();
        float4 av = *(const float4*)(X + (size_t)(m0 + arow) * 1024 + k0 + akq);
        As[akq + 0][arow] = av.x;
        As[akq + 1][arow] = av.y;
        As[akq + 2][arow] = av.z;
        As[akq + 3][arow] = av.w;
        float4 bv = *(const float4*)(W + (size_t)(k0 + bk) * 3072 + n0 + bnq);
        *(float4*)&Bs[bk][bnq] = bv;
        __syncthreads();
#pragma unroll
        for (int kk = 0; kk < 8; kk++) {
            float4 a0 = *(float4*)&As[kk][ty * 4];
            float4 a1 = *(float4*)&As[kk][64 + ty * 4];
            float4 b0 = *(float4*)&Bs[kk][tx * 4];
            float4 b1 = *(float4*)&Bs[kk][64 + tx * 4];
            float af[8] = {a0.x, a0.y, a0.z, a0.w, a1.x, a1.y, a1.z, a1.w};
            float bf[8] = {b0.x, b0.y, b0.z, b0.w, b1.x, b1.y, b1.z, b1.w};
#pragma unroll
            for (int i = 0; i < 8; i++)
#pragma unroll
                for (int j = 0; j < 8; j++) acc[i][j] += af[i] * bf[j];
        }
    }

    // Epilogue: scatter to q/k/v [B,H,T,D]. A 128-col block lies entirely in
    // one of q/k/v (3072/128=24 blocks, 8 per segment) and spans 2 heads.
    const int seg = n0 >> 10;             // 0=q 1=k 2=v
    float* dst = (seg == 0) ? g_q : (seg == 1) ? g_k : g_v;
    const float scale = (seg == 0) ? 0.125f : 1.0f;  // 1/sqrt(64)
    const int h0 = (n0 & 1023) >> 6;
    const int d = tx * 4;
#pragma unroll
    for (int jg = 0; jg < 2; jg++) {
        const int h = h0 + jg;
        float4 bb = *(const float4*)(bias + n0 + jg * 64 + d);
#pragma unroll
        for (int ig = 0; ig < 2; ig++) {
#pragma unroll
            for (int i = 0; i < 4; i++) {
                const int m = m0 + ig * 64 + ty * 4 + i;
                const int b = m >> 11;       // /T
                const int t = m & 2047;      // %T
                const int ai = ig * 4 + i, aj = jg * 4;
                float4 o;
                o.x = (acc[ai][aj + 0] + bb.x) * scale;
                o.y = (acc[ai][aj + 1] + bb.y) * scale;
                o.z = (acc[ai][aj + 2] + bb.z) * scale;
                o.w = (acc[ai][aj + 3] + bb.w) * scale;
                *(float4*)(dst + ((size_t)(b * Hn + h) * Tn + t) * Dn + d) = o;
            }
        }
    }
}

// ---------------------------------------------------------------------------
// GEMM2: out = y[8192,1024] @ W_proj[1024,1024] + b_proj
// ---------------------------------------------------------------------------
__global__ __launch_bounds__(256) void gemm_proj_kernel(
    const float* __restrict__ W, const float* __restrict__ bias,
    float* __restrict__ out)
{
    __shared__ float As[8][128];
    __shared__ float Bs[8][128];
    const int tid = threadIdx.x;
    const int tx = tid & 15, ty = tid >> 4;
    const int m0 = blockIdx.y * 128;
    const int n0 = blockIdx.x * 128;

    const int arow = tid >> 1, akq = (tid & 1) * 4;
    const int bk = tid >> 5, bnq = (tid & 31) * 4;

    float acc[8][8];
#pragma unroll
    for (int i = 0; i < 8; i++)
#pragma unroll
        for (int j = 0; j < 8; j++) acc[i][j] = 0.0f;

    for (int k0 = 0; k0 < 1024; k0 += 8) {
        __syncthreads();
        float4 av = *(const float4*)(g_y + (size_t)(m0 + arow) * 1024 + k0 + akq);
        As[akq + 0][arow] = av.x;
        As[akq + 1][arow] = av.y;
        As[akq + 2][arow] = av.z;
        As[akq + 3][arow] = av.w;
        float4 bv = *(const float4*)(W + (size_t)(k0 + bk) * 1024 + n0 + bnq);
        *(float4*)&Bs[bk][bnq] = bv;
        __syncthreads();
#pragma unroll
        for (int kk = 0; kk < 8; kk++) {
            float4 a0 = *(float4*)&As[kk][ty * 4];
            float4 a1 = *(float4*)&As[kk][64 + ty * 4];
            float4 b0 = *(float4*)&Bs[kk][tx * 4];
            float4 b1 = *(float4*)&Bs[kk][64 + tx * 4];
            float af[8] = {a0.x, a0.y, a0.z, a0.w, a1.x, a1.y, a1.z, a1.w};
            float bf[8] = {b0.x, b0.y, b0.z, b0.w, b1.x, b1.y, b1.z, b1.w};
#pragma unroll
            for (int i = 0; i < 8; i++)
#pragma unroll
                for (int j = 0; j < 8; j++) acc[i][j] += af[i] * bf[j];
        }
    }

#pragma unroll
    for (int jg = 0; jg < 2; jg++) {
        const int n = n0 + jg * 64 + tx * 4;
        float4 bb = *(const float4*)(bias + n);
#pragma unroll
        for (int ig = 0; ig < 2; ig++) {
#pragma unroll
            for (int i = 0; i < 4; i++) {
                const int m = m0 + ig * 64 + ty * 4 + i;
                const int ai = ig * 4 + i, aj = jg * 4;
                float4 o;
                o.x = acc[ai][aj + 0] + bb.x;
                o.y = acc[ai][aj + 1] + bb.y;
                o.z = acc[ai][aj + 2] + bb.z;
                o.w = acc[ai][aj + 3] + bb.w;
                *(float4*)(out + (size_t)m * 1024 + n) = o;
            }
        }
    }
}

// ---------------------------------------------------------------------------
// Flash attention: one CTA per (b*h, q-tile of 64 rows). BLOCK_N=64, D=64.
// 256 threads as 16x16; each thread owns a 4(row) x 4(col) fragment.
// Causal: only kt <= qi tiles visited; diagonal tile masked.
// ---------------------------------------------------------------------------
#define SSTR 68  // smem row stride (floats): mult of 4 for float4, !=64 for banks

__global__ __launch_bounds__(256) void attn_kernel()
{
    extern __shared__ float sm[];
    float* Qs = sm;                // [D][SSTR] transposed: Qs[d*SSTR + m]
    float* Ks = Qs + 64 * SSTR;    // [D][SSTR] transposed: Ks[d*SSTR + n]
    float* Vs = Ks + 64 * SSTR;    // [N][SSTR] natural:    Vs[k*SSTR + d]
    float* Ps = Vs + 64 * SSTR;    // [M][SSTR] natural:    Ps[m*SSTR + k]

    const int tid = threadIdx.x;
    const int tx = tid & 15, ty = tid >> 4;
    const int qi = blockIdx.x;
    const int bh = blockIdx.y;

    const float* qg = g_q + (size_t)bh * Tn * Dn + (size_t)qi * 64 * Dn;
    const float* kg = g_k + (size_t)bh * Tn * Dn;
    const float* vg = g_v + (size_t)bh * Tn * Dn;

    // Load Q tile (transposed into smem); 1/sqrt(D) already folded in.
#pragma unroll
    for (int i = 0; i < 4; i++) {
        const int lin = tid + i * 256;   // float4 index, 1024 total
        const int row = lin >> 4;
        const int c4 = (lin & 15) * 4;
        float4 v = *(const float4*)(qg + row * 64 + c4);
        Qs[(c4 + 0) * SSTR + row] = v.x;
        Qs[(c4 + 1) * SSTR + row] = v.y;
        Qs[(c4 + 2) * SSTR + row] = v.z;
        Qs[(c4 + 3) * SSTR + row] = v.w;
    }

    float m_i[4], l_i[4], acc[4][4];
#pragma unroll
    for (int i = 0; i < 4; i++) {
        m_i[i] = -1e30f;
        l_i[i] = 0.0f;
#pragma unroll
        for (int j = 0; j < 4; j++) acc[i][j] = 0.0f;
    }

    const int qrow_base = qi * 64 + ty * 4;

    for (int kt = 0; kt <= qi; kt++) {
        __syncthreads();
        const float* kp = kg + (size_t)kt * 64 * Dn;
        const float* vp = vg + (size_t)kt * 64 * Dn;
#pragma unroll
        for (int i = 0; i < 4; i++) {
            const int lin = tid + i * 256;
            const int row = lin >> 4;
            const int c4 = (lin & 15) * 4;
            float4 kv = *(const float4*)(kp + row * 64 + c4);
            Ks[(c4 + 0) * SSTR + row] = kv.x;
            Ks[(c4 + 1) * SSTR + row] = kv.y;
            Ks[(c4 + 2) * SSTR + row] = kv.z;
            Ks[(c4 + 3) * SSTR + row] = kv.w;
            float4 vv = *(const float4*)(vp + row * 64 + c4);
            *(float4*)&Vs[row * SSTR + c4] = vv;
        }
        __syncthreads();

        // S = Q K^T (q pre-scaled)
        float s[4][4];
#pragma unroll
        for (int i = 0; i < 4; i++)
#pragma unroll
            for (int j = 0; j < 4; j++) s[i][j] = 0.0f;
#pragma unroll 16
        for (int dd = 0; dd < 64; dd++) {
            float4 qf = *(float4*)&Qs[dd * SSTR + ty * 4];
            float4 kf = *(float4*)&Ks[dd * SSTR + tx * 4];
            float qa[4] = {qf.x, qf.y, qf.z, qf.w};
            float ka[4] = {kf.x, kf.y, kf.z, kf.w};
#pragma unroll
            for (int i = 0; i < 4; i++)
#pragma unroll
                for (int j = 0; j < 4; j++) s[i][j] += qa[i] * ka[j];
        }

        if (kt == qi) {  // diagonal tile: causal mask
#pragma unroll
            for (int i = 0; i < 4; i++)
#pragma unroll
                for (int j = 0; j < 4; j++)
                    if (kt * 64 + tx * 4 + j > qrow_base + i) s[i][j] = -1e30f;
        }

        // online softmax update
        float mnew[4];
#pragma unroll
        for (int i = 0; i < 4; i++) {
            float v = fmaxf(fmaxf(s[i][0], s[i][1]), fmaxf(s[i][2], s[i][3]));
#pragma unroll
            for (int off = 1; off < 16; off <<= 1)
                v = fmaxf(v, __shfl_xor_sync(0xffffffffu, v, off));
            mnew[i] = fmaxf(m_i[i], v);
        }
#pragma unroll
        for (int i = 0; i < 4; i++) {
            const float a = __expf(m_i[i] - mnew[i]);
            m_i[i] = mnew[i];
            float r = 0.0f;
#pragma unroll
            for (int j = 0; j < 4; j++) {
                s[i][j] = __expf(s[i][j] - mnew[i]);
                r += s[i][j];
            }
#pragma unroll
            for (int off = 1; off < 16; off <<= 1)
                r += __shfl_xor_sync(0xffffffffu, r, off);
            l_i[i] = l_i[i] * a + r;
#pragma unroll
            for (int j = 0; j < 4; j++) acc[i][j] *= a;
        }

        // stage P (natural layout, conflict-free float4 stores)
#pragma unroll
        for (int i = 0; i < 4; i++)
            *(float4*)&Ps[(ty * 4 + i) * SSTR + tx * 4] =
                make_float4(s[i][0], s[i][1], s[i][2], s[i][3]);
        __syncthreads();

        // O += P @ V
#pragma unroll 16
        for (int k = 0; k < 64; k++) {
            float p0 = Ps[(ty * 4 + 0) * SSTR + k];
            float p1 = Ps[(ty * 4 + 1) * SSTR + k];
            float p2 = Ps[(ty * 4 + 2) * SSTR + k];
            float p3 = Ps[(ty * 4 + 3) * SSTR + k];
            float4 vf = *(float4*)&Vs[k * SSTR + tx * 4];
            acc[0][0] += p0 * vf.x; acc[0][1] += p0 * vf.y; acc[0][2] += p0 * vf.z; acc[0][3] += p0 * vf.w;
            acc[1][0] += p1 * vf.x; acc[1][1] += p1 * vf.y; acc[1][2] += p1 * vf.z; acc[1][3] += p1 * vf.w;
            acc[2][0] += p2 * vf.x; acc[2][1] += p2 * vf.y; acc[2][2] += p2 * vf.z; acc[2][3] += p2 * vf.w;
            acc[3][0] += p3 * vf.x; acc[3][1] += p3 * vf.y; acc[3][2] += p3 * vf.z; acc[3][3] += p3 * vf.w;
        }
    }

    // write y[b, t, h*64+d]
    const int b = bh >> 4, h = bh & 15;
#pragma unroll
    for (int i = 0; i < 4; i++) {
        const float inv = 1.0f / l_i[i];
        const int t = qi * 64 + ty * 4 + i;
        float4 o = make_float4(acc[i][0] * inv, acc[i][1] * inv,
                               acc[i][2] * inv, acc[i][3] * inv);
        *(float4*)(g_y + ((size_t)(b * Tn + t)) * Cn + h * 64 + tx * 4) = o;
    }
}

// ---------------------------------------------------------------------------
extern "C" void kernel_launch(void* const* d_in, const int* in_sizes, int n_in,
                              void* d_out, int out_size)
{
    const float* x      = (const float*)d_in[0];
    const float* W_attn = (const float*)d_in[1];
    const float* b_attn = (const float*)d_in[2];
    const float* W_proj = (const float*)d_in[3];
    const float* b_proj = (const float*)d_in[4];
    float* out = (float*)d_out;

    dim3 blk(256);
    gemm_qkv_kernel<<<dim3(24, 64), blk>>>(x, W_attn, b_attn);

    const int smem = 4 * 64 * SSTR * (int)sizeof(float);  // 69632 B
    cudaFuncSetAttribute(attn_kernel,
                         cudaFuncAttributeMaxDynamicSharedMemorySize, smem);
    attn_kernel<<<dim3(Tn / 64, Bsz * Hn), blk, smem>>>();

    gemm_proj_kernel<<<dim3(8, 64), blk>>>(W_proj, b_proj, out);
}

// round 5
// speedup vs baseline: 1.4712x; 1.4712x over previous
#include <cuda_runtime.h>
#include <cuda_bf16.h>
#include <cstdint>

#define Bsz 4
#define Tn 2048
#define Cn 1024
#define Hn 16
#define Dn 64
#define NTOK (Bsz*Tn)   // 8192

// ---------------------------------------------------------------------------
// Scratch (device globals: allocation-free)
// ---------------------------------------------------------------------------
__device__ float g_q[Bsz*Hn*Tn*Dn];
__device__ float g_k[Bsz*Hn*Tn*Dn];
__device__ float g_v[Bsz*Hn*Tn*Dn];
__device__ float g_y[Bsz*Tn*Cn];

__device__ __align__(16) __nv_bfloat16 g_xhi[NTOK*Cn];
__device__ __align__(16) __nv_bfloat16 g_xlo[NTOK*Cn];
__device__ __align__(16) __nv_bfloat16 g_yhi[NTOK*Cn];
__device__ __align__(16) __nv_bfloat16 g_ylo[NTOK*Cn];
__device__ __align__(16) __nv_bfloat16 g_wahi[3*Cn*Cn];   // W_attn^T [3072][1024]
__device__ __align__(16) __nv_bfloat16 g_walo[3*Cn*Cn];
__device__ __align__(16) __nv_bfloat16 g_wphi[Cn*Cn];     // W_proj^T [1024][1024]
__device__ __align__(16) __nv_bfloat16 g_wplo[Cn*Cn];

// ---------------------------------------------------------------------------
// Baseline-PTX helpers (sm_80-level: compile for sm_103 non-'a' target)
// ---------------------------------------------------------------------------
__device__ __forceinline__ uint32_t smem_to_u32(const void* p) {
    uint32_t a;
    asm("{ .reg .u64 t; cvta.to.shared.u64 t, %1; cvt.u32.u64 %0, t; }"
        : "=r"(a) : "l"(p));
    return a;
}
#define CP_ASYNC16(dst_u32, src_ptr) \
    asm volatile("cp.async.cg.shared.global [%0], [%1], 16;" \
        :: "r"(dst_u32), "l"(src_ptr))
#define CP_COMMIT() asm volatile("cp.async.commit_group;" ::: "memory")
#define CP_WAIT0()  asm volatile("cp.async.wait_group 0;" ::: "memory")

__device__ __forceinline__ void ldsm4(uint32_t* r, uint32_t addr) {
    asm volatile("ldmatrix.sync.aligned.m8n8.x4.shared.b16 {%0,%1,%2,%3}, [%4];"
        : "=r"(r[0]), "=r"(r[1]), "=r"(r[2]), "=r"(r[3]) : "r"(addr));
}
__device__ __forceinline__ void mma16816(float* d, const uint32_t* a,
                                         uint32_t b0, uint32_t b1) {
    asm volatile(
        "mma.sync.aligned.m16n8k16.row.col.f32.bf16.bf16.f32 "
        "{%0,%1,%2,%3}, {%4,%5,%6,%7}, {%8,%9}, {%0,%1,%2,%3};"
        : "+f"(d[0]), "+f"(d[1]), "+f"(d[2]), "+f"(d[3])
        : "r"(a[0]), "r"(a[1]), "r"(a[2]), "r"(a[3]), "r"(b0), "r"(b1));
}

// ---------------------------------------------------------------------------
// fp32 -> bf16 hi/lo split
// ---------------------------------------------------------------------------
__global__ __launch_bounds__(256) void split_kernel(
    const float* __restrict__ in, __nv_bfloat16* __restrict__ hi,
    __nv_bfloat16* __restrict__ lo, int n4)
{
    int idx = blockIdx.x * 256 + threadIdx.x;
    if (idx >= n4) return;
    float4 v = *(const float4*)(in + (size_t)idx * 4);
    __nv_bfloat16 h0 = __float2bfloat16(v.x);
    __nv_bfloat16 h1 = __float2bfloat16(v.y);
    __nv_bfloat16 h2 = __float2bfloat16(v.z);
    __nv_bfloat16 h3 = __float2bfloat16(v.w);
    __nv_bfloat162* hp = (__nv_bfloat162*)hi;
    __nv_bfloat162* lp = (__nv_bfloat162*)lo;
    hp[idx * 2 + 0] = __nv_bfloat162(h0, h1);
    hp[idx * 2 + 1] = __nv_bfloat162(h2, h3);
    lp[idx * 2 + 0] = __nv_bfloat162(
        __float2bfloat16(v.x - __bfloat162float(h0)),
        __float2bfloat16(v.y - __bfloat162float(h1)));
    lp[idx * 2 + 1] = __nv_bfloat162(
        __float2bfloat16(v.z - __bfloat162float(h2)),
        __float2bfloat16(v.w - __bfloat162float(h3)));
}

// Transpose + split: W[K,N] fp32 -> T[N,K] bf16 hi/lo
__global__ __launch_bounds__(256) void wsplit_kernel(
    const float* __restrict__ W, __nv_bfloat16* __restrict__ Thi,
    __nv_bfloat16* __restrict__ Tlo, int Krows, int Ncols)
{
    __shared__ float s[32][33];
    const int n0 = blockIdx.x * 32, k0 = blockIdx.y * 32;
    const int tx = threadIdx.x & 31, ty = threadIdx.x >> 5;  // 32x8
#pragma unroll
    for (int i = 0; i < 4; i++) {
        int k = k0 + ty + i * 8;
        s[ty + i * 8][tx] = W[(size_t)k * Ncols + n0 + tx];
    }
    __syncthreads();
#pragma unroll
    for (int i = 0; i < 4; i++) {
        int n = n0 + ty + i * 8;
        float v = s[tx][ty + i * 8];
        __nv_bfloat16 h = __float2bfloat16(v);
        Thi[(size_t)n * Krows + k0 + tx] = h;
        Tlo[(size_t)n * Krows + k0 + tx] =
            __float2bfloat16(v - __bfloat162float(h));
    }
}

// ---------------------------------------------------------------------------
// HMMA GEMM: D[128,128] per CTA = A[m0:,K] * Bt[n0:,K]^T, K=1024, bf16 split.
// 8 warps (2x4), warp tile 64x32. K-chunk 64; smem rows 128B, chunk^=(row&7)
// swizzle for conflict-free ldmatrix. 2-stage cp.async pipeline.
// MODE 0: scatter q/k/v + bias (+q scale). MODE 1: bias + write out.
// ---------------------------------------------------------------------------
#define STG_BYTES 65536   // 4 operands x 16KB
template <int MODE>
__global__ __launch_bounds__(256) void gemm_mma_kernel(
    const __nv_bfloat16* __restrict__ Ahi, const __nv_bfloat16* __restrict__ Alo,
    const __nv_bfloat16* __restrict__ Bhi, const __nv_bfloat16* __restrict__ Blo,
    const float* __restrict__ bias, float* __restrict__ out)
{
    extern __shared__ char smem[];
    const uint32_t smem_u = smem_to_u32(smem);
    const int tid = threadIdx.x;
    const int lane = tid & 31;
    const int warp = tid >> 5;
    const int wm = warp >> 2;          // 0..1
    const int wn = warp & 3;           // 0..3
    const int m0 = blockIdx.y * 128;
    const int n0 = blockIdx.x * 128;

    // ---- per-thread cp.async mapping (4 x 16B chunks per operand) ----
    int lrow[4], lso[4];
#pragma unroll
    for (int i = 0; i < 4; i++) {
        const int c = tid + i * 256;          // 0..1023
        const int row = c >> 3, col = c & 7;
        lrow[i] = row;
        lso[i] = row * 128 + ((col ^ (row & 7)) * 16);
    }

    float acc[4][4][4];
#pragma unroll
    for (int i = 0; i < 4; i++)
#pragma unroll
        for (int j = 0; j < 4; j++)
#pragma unroll
            for (int q = 0; q < 4; q++) acc[i][j][q] = 0.0f;

    // prefetch chunk 0 -> stage 0
    {
        const uint32_t sb = smem_u;
#pragma unroll
        for (int i = 0; i < 4; i++) {
            const int col = (tid + i * 256) & 7;
            const size_t ga = (size_t)(m0 + lrow[i]) * 1024 + col * 8;
            const size_t gb = (size_t)(n0 + lrow[i]) * 1024 + col * 8;
            CP_ASYNC16(sb + lso[i],          Ahi + ga);
            CP_ASYNC16(sb + 16384 + lso[i],  Alo + ga);
            CP_ASYNC16(sb + 32768 + lso[i],  Bhi + gb);
            CP_ASYNC16(sb + 49152 + lso[i],  Blo + gb);
        }
        CP_COMMIT();
    }

    for (int c = 0; c < 16; ++c) {
        CP_WAIT0();
        __syncthreads();
        if (c + 1 < 16) {
            const int k0 = (c + 1) * 64;
            const uint32_t sb = smem_u + ((c + 1) & 1) * STG_BYTES;
#pragma unroll
            for (int i = 0; i < 4; i++) {
                const int col = (tid + i * 256) & 7;
                const size_t ga = (size_t)(m0 + lrow[i]) * 1024 + k0 + col * 8;
                const size_t gb = (size_t)(n0 + lrow[i]) * 1024 + k0 + col * 8;
                CP_ASYNC16(sb + lso[i],          Ahi + ga);
                CP_ASYNC16(sb + 16384 + lso[i],  Alo + ga);
                CP_ASYNC16(sb + 32768 + lso[i],  Bhi + gb);
                CP_ASYNC16(sb + 49152 + lso[i],  Blo + gb);
            }
            CP_COMMIT();
        }

        const uint32_t sA  = smem_u + (c & 1) * STG_BYTES;
        const uint32_t sAl = sA + 16384;
        const uint32_t sBh = sA + 32768;
        const uint32_t sBl = sA + 49152;

#pragma unroll
        for (int ks = 0; ks < 4; ks++) {
            uint32_t ahi[4][4], alo[4][4];
#pragma unroll
            for (int i = 0; i < 4; i++) {
                const int r = wm * 64 + i * 16 + (lane & 15);
                const int ch = ks * 2 + (lane >> 4);
                const uint32_t off = r * 128 + ((ch ^ (r & 7)) * 16);
                ldsm4(ahi[i], sA + off);
                ldsm4(alo[i], sAl + off);
            }
            uint32_t bhi[2][4], blo[2][4];
#pragma unroll
            for (int jh = 0; jh < 2; jh++) {
                const int r = wn * 32 + jh * 16 + (lane & 15);
                const int ch = ks * 2 + (lane >> 4);
                const uint32_t off = r * 128 + ((ch ^ (r & 7)) * 16);
                ldsm4(bhi[jh], sBh + off);
                ldsm4(blo[jh], sBl + off);
            }
#pragma unroll
            for (int i = 0; i < 4; i++) {
#pragma unroll
                for (int j = 0; j < 4; j++) {
                    const int jh = j >> 1, sel = j & 1;
                    mma16816(acc[i][j], ahi[i], bhi[jh][sel], bhi[jh][sel + 2]);
                    mma16816(acc[i][j], ahi[i], blo[jh][sel], blo[jh][sel + 2]);
                    mma16816(acc[i][j], alo[i], bhi[jh][sel], bhi[jh][sel + 2]);
                }
            }
        }
        __syncthreads();
    }

    // ---- epilogue ----
    const int mrow0 = m0 + wm * 64 + (lane >> 2);
    const int ncol0 = n0 + wn * 32 + (lane & 3) * 2;
#pragma unroll
    for (int i = 0; i < 4; i++) {
#pragma unroll
        for (int j = 0; j < 4; j++) {
            const int n = ncol0 + j * 8;
            const float b0 = bias[n], b1 = bias[n + 1];
#pragma unroll
            for (int half = 0; half < 2; half++) {
                const int m = mrow0 + i * 16 + half * 8;
                const float v0 = acc[i][j][half * 2 + 0] + b0;
                const float v1 = acc[i][j][half * 2 + 1] + b1;
                if (MODE == 0) {
                    const int seg = n >> 10;
                    float* dst = (seg == 0) ? g_q : (seg == 1) ? g_k : g_v;
                    const float scale = (seg == 0) ? 0.125f : 1.0f;
                    const int h = (n & 1023) >> 6;
                    const int b = m >> 11, t = m & 2047;
                    float2 o = make_float2(v0 * scale, v1 * scale);
                    *(float2*)(dst + ((size_t)(b * Hn + h) * Tn + t) * Dn
                               + (n & 63)) = o;
                } else {
                    *(float2*)(out + (size_t)m * 1024 + n) =
                        make_float2(v0, v1);
                }
            }
        }
    }
}

// ---------------------------------------------------------------------------
// Flash attention (SIMT fp32, unchanged): one CTA per (b*h, 64-row q tile).
// ---------------------------------------------------------------------------
#define SSTR 68

__global__ __launch_bounds__(256) void attn_kernel()
{
    extern __shared__ float sm[];
    float* Qs = sm;
    float* Ks = Qs + 64 * SSTR;
    float* Vs = Ks + 64 * SSTR;
    float* Ps = Vs + 64 * SSTR;

    const int tid = threadIdx.x;
    const int tx = tid & 15, ty = tid >> 4;
    const int qi = blockIdx.x;
    const int bh = blockIdx.y;

    const float* qg = g_q + (size_t)bh * Tn * Dn + (size_t)qi * 64 * Dn;
    const float* kg = g_k + (size_t)bh * Tn * Dn;
    const float* vg = g_v + (size_t)bh * Tn * Dn;

#pragma unroll
    for (int i = 0; i < 4; i++) {
        const int lin = tid + i * 256;
        const int row = lin >> 4;
        const int c4 = (lin & 15) * 4;
        float4 v = *(const float4*)(qg + row * 64 + c4);
        Qs[(c4 + 0) * SSTR + row] = v.x;
        Qs[(c4 + 1) * SSTR + row] = v.y;
        Qs[(c4 + 2) * SSTR + row] = v.z;
        Qs[(c4 + 3) * SSTR + row] = v.w;
    }

    float m_i[4], l_i[4], acc[4][4];
#pragma unroll
    for (int i = 0; i < 4; i++) {
        m_i[i] = -1e30f;
        l_i[i] = 0.0f;
#pragma unroll
        for (int j = 0; j < 4; j++) acc[i][j] = 0.0f;
    }

    const int qrow_base = qi * 64 + ty * 4;

    for (int kt = 0; kt <= qi; kt++) {
        __syncthreads();
        const float* kp = kg + (size_t)kt * 64 * Dn;
        const float* vp = vg + (size_t)kt * 64 * Dn;
#pragma unroll
        for (int i = 0; i < 4; i++) {
            const int lin = tid + i * 256;
            const int row = lin >> 4;
            const int c4 = (lin & 15) * 4;
            float4 kv = *(const float4*)(kp + row * 64 + c4);
            Ks[(c4 + 0) * SSTR + row] = kv.x;
            Ks[(c4 + 1) * SSTR + row] = kv.y;
            Ks[(c4 + 2) * SSTR + row] = kv.z;
            Ks[(c4 + 3) * SSTR + row] = kv.w;
            float4 vv = *(const float4*)(vp + row * 64 + c4);
            *(float4*)&Vs[row * SSTR + c4] = vv;
        }
        __syncthreads();

        float s[4][4];
#pragma unroll
        for (int i = 0; i < 4; i++)
#pragma unroll
            for (int j = 0; j < 4; j++) s[i][j] = 0.0f;
#pragma unroll 16
        for (int dd = 0; dd < 64; dd++) {
            float4 qf = *(float4*)&Qs[dd * SSTR + ty * 4];
            float4 kf = *(float4*)&Ks[dd * SSTR + tx * 4];
            float qa[4] = {qf.x, qf.y, qf.z, qf.w};
            float ka[4] = {kf.x, kf.y, kf.z, kf.w};
#pragma unroll
            for (int i = 0; i < 4; i++)
#pragma unroll
                for (int j = 0; j < 4; j++) s[i][j] += qa[i] * ka[j];
        }

        if (kt == qi) {
#pragma unroll
            for (int i = 0; i < 4; i++)
#pragma unroll
                for (int j = 0; j < 4; j++)
                    if (kt * 64 + tx * 4 + j > qrow_base + i) s[i][j] = -1e30f;
        }

        float mnew[4];
#pragma unroll
        for (int i = 0; i < 4; i++) {
            float v = fmaxf(fmaxf(s[i][0], s[i][1]), fmaxf(s[i][2], s[i][3]));
#pragma unroll
            for (int off = 1; off < 16; off <<= 1)
                v = fmaxf(v, __shfl_xor_sync(0xffffffffu, v, off));
            mnew[i] = fmaxf(m_i[i], v);
        }
#pragma unroll
        for (int i = 0; i < 4; i++) {
            const float a = __expf(m_i[i] - mnew[i]);
            m_i[i] = mnew[i];
            float r = 0.0f;
#pragma unroll
            for (int j = 0; j < 4; j++) {
                s[i][j] = __expf(s[i][j] - mnew[i]);
                r += s[i][j];
            }
#pragma unroll
            for (int off = 1; off < 16; off <<= 1)
                r += __shfl_xor_sync(0xffffffffu, r, off);
            l_i[i] = l_i[i] * a + r;
#pragma unroll
            for (int j = 0; j < 4; j++) acc[i][j] *= a;
        }

#pragma unroll
        for (int i = 0; i < 4; i++)
            *(float4*)&Ps[(ty * 4 + i) * SSTR + tx * 4] =
                make_float4(s[i][0], s[i][1], s[i][2], s[i][3]);
        __syncthreads();

#pragma unroll 16
        for (int k = 0; k < 64; k++) {
            float p0 = Ps[(ty * 4 + 0) * SSTR + k];
            float p1 = Ps[(ty * 4 + 1) * SSTR + k];
            float p2 = Ps[(ty * 4 + 2) * SSTR + k];
            float p3 = Ps[(ty * 4 + 3) * SSTR + k];
            float4 vf = *(float4*)&Vs[k * SSTR + tx * 4];
            acc[0][0] += p0 * vf.x; acc[0][1] += p0 * vf.y; acc[0][2] += p0 * vf.z; acc[0][3] += p0 * vf.w;
            acc[1][0] += p1 * vf.x; acc[1][1] += p1 * vf.y; acc[1][2] += p1 * vf.z; acc[1][3] += p1 * vf.w;
            acc[2][0] += p2 * vf.x; acc[2][1] += p2 * vf.y; acc[2][2] += p2 * vf.z; acc[2][3] += p2 * vf.w;
            acc[3][0] += p3 * vf.x; acc[3][1] += p3 * vf.y; acc[3][2] += p3 * vf.z; acc[3][3] += p3 * vf.w;
        }
    }

    const int b = bh >> 4, h = bh & 15;
#pragma unroll
    for (int i = 0; i < 4; i++) {
        const float inv = 1.0f / l_i[i];
        const int t = qi * 64 + ty * 4 + i;
        float4 o = make_float4(acc[i][0] * inv, acc[i][1] * inv,
                               acc[i][2] * inv, acc[i][3] * inv);
        *(float4*)(g_y + ((size_t)(b * Tn + t)) * Cn + h * 64 + tx * 4) = o;
    }
}

// ---------------------------------------------------------------------------
extern "C" void kernel_launch(void* const* d_in, const int* in_sizes, int n_in,
                              void* d_out, int out_size)
{
    const float* x      = (const float*)d_in[0];
    const float* W_attn = (const float*)d_in[1];
    const float* b_attn = (const float*)d_in[2];
    const float* W_proj = (const float*)d_in[3];
    const float* b_proj = (const float*)d_in[4];
    float* out = (float*)d_out;

    __nv_bfloat16 *xhi, *xlo, *yhi, *ylo, *wahi, *walo, *wphi, *wplo;
    float *yv;
    cudaGetSymbolAddress((void**)&xhi,  g_xhi);
    cudaGetSymbolAddress((void**)&xlo,  g_xlo);
    cudaGetSymbolAddress((void**)&yhi,  g_yhi);
    cudaGetSymbolAddress((void**)&ylo,  g_ylo);
    cudaGetSymbolAddress((void**)&wahi, g_wahi);
    cudaGetSymbolAddress((void**)&walo, g_walo);
    cudaGetSymbolAddress((void**)&wphi, g_wphi);
    cudaGetSymbolAddress((void**)&wplo, g_wplo);
    cudaGetSymbolAddress((void**)&yv,   g_y);

    const int gemm_smem = 2 * STG_BYTES;  // 131072 B
    cudaFuncSetAttribute(gemm_mma_kernel<0>,
                         cudaFuncAttributeMaxDynamicSharedMemorySize, gemm_smem);
    cudaFuncSetAttribute(gemm_mma_kernel<1>,
                         cudaFuncAttributeMaxDynamicSharedMemorySize, gemm_smem);
    const int attn_smem = 4 * 64 * SSTR * (int)sizeof(float);  // 69632 B
    cudaFuncSetAttribute(attn_kernel,
                         cudaFuncAttributeMaxDynamicSharedMemorySize, attn_smem);

    // 1) splits
    split_kernel<<<NTOK * Cn / 4 / 256, 256>>>(x, xhi, xlo, NTOK * Cn / 4);
    wsplit_kernel<<<dim3(3 * Cn / 32, Cn / 32), 256>>>(W_attn, wahi, walo, Cn, 3 * Cn);
    wsplit_kernel<<<dim3(Cn / 32, Cn / 32), 256>>>(W_proj, wphi, wplo, Cn, Cn);

    // 2) qkv = x @ W_attn + b  (HMMA, scatter to q/k/v)
    gemm_mma_kernel<0><<<dim3(24, 64), 256, gemm_smem>>>(
        xhi, xlo, wahi, walo, b_attn, nullptr);

    // 3) attention -> g_y
    attn_kernel<<<dim3(Tn / 64, Bsz * Hn), 256, attn_smem>>>();

    // 4) split y, proj GEMM -> out
    split_kernel<<<NTOK * Cn / 4 / 256, 256>>>(yv, yhi, ylo, NTOK * Cn / 4);
    gemm_mma_kernel<1><<<dim3(8, 64), 256, gemm_smem>>>(
        yhi, ylo, wphi, wplo, b_proj, out);
}

// round 6
// speedup vs baseline: 2.5960x; 1.7646x over previous
#include <cuda_runtime.h>
#include <cuda_bf16.h>
#include <cstdint>

#define Bsz 4
#define Tn 2048
#define Cn 1024
#define Hn 16
#define Dn 64
#define NTOK (Bsz*Tn)   // 8192

// ---------------------------------------------------------------------------
// Scratch (device globals: allocation-free)
// ---------------------------------------------------------------------------
__device__ __align__(16) __nv_bfloat16 g_xhi[NTOK*Cn];
__device__ __align__(16) __nv_bfloat16 g_xlo[NTOK*Cn];
__device__ __align__(16) __nv_bfloat16 g_yhi[NTOK*Cn];
__device__ __align__(16) __nv_bfloat16 g_ylo[NTOK*Cn];
__device__ __align__(16) __nv_bfloat16 g_wahi[3*Cn*Cn];   // W_attn^T [3072][1024]
__device__ __align__(16) __nv_bfloat16 g_walo[3*Cn*Cn];
__device__ __align__(16) __nv_bfloat16 g_wphi[Cn*Cn];     // W_proj^T [1024][1024]
__device__ __align__(16) __nv_bfloat16 g_wplo[Cn*Cn];
// q/k/v as bf16 hi/lo, layout [B,H,T,D]
__device__ __align__(16) __nv_bfloat16 g_qhi[Bsz*Hn*Tn*Dn];
__device__ __align__(16) __nv_bfloat16 g_qlo[Bsz*Hn*Tn*Dn];
__device__ __align__(16) __nv_bfloat16 g_khi[Bsz*Hn*Tn*Dn];
__device__ __align__(16) __nv_bfloat16 g_klo[Bsz*Hn*Tn*Dn];
__device__ __align__(16) __nv_bfloat16 g_vhi[Bsz*Hn*Tn*Dn];
__device__ __align__(16) __nv_bfloat16 g_vlo[Bsz*Hn*Tn*Dn];

// ---------------------------------------------------------------------------
// Baseline-PTX helpers (sm_80-level; compile for plain sm_103 target)
// ---------------------------------------------------------------------------
__device__ __forceinline__ uint32_t smem_to_u32(const void* p) {
    uint32_t a;
    asm("{ .reg .u64 t; cvta.to.shared.u64 t, %1; cvt.u32.u64 %0, t; }"
        : "=r"(a) : "l"(p));
    return a;
}
#define CP_ASYNC16(dst_u32, src_ptr) \
    asm volatile("cp.async.cg.shared.global [%0], [%1], 16;" \
        :: "r"(dst_u32), "l"(src_ptr))
#define CP_COMMIT() asm volatile("cp.async.commit_group;" ::: "memory")
#define CP_WAIT0()  asm volatile("cp.async.wait_group 0;" ::: "memory")

__device__ __forceinline__ void ldsm4(uint32_t* r, uint32_t addr) {
    asm volatile("ldmatrix.sync.aligned.m8n8.x4.shared.b16 {%0,%1,%2,%3}, [%4];"
        : "=r"(r[0]), "=r"(r[1]), "=r"(r[2]), "=r"(r[3]) : "r"(addr));
}
__device__ __forceinline__ void ldsm4t(uint32_t* r, uint32_t addr) {
    asm volatile("ldmatrix.sync.aligned.m8n8.x4.trans.shared.b16 {%0,%1,%2,%3}, [%4];"
        : "=r"(r[0]), "=r"(r[1]), "=r"(r[2]), "=r"(r[3]) : "r"(addr));
}
__device__ __forceinline__ void mma16816(float* d, const uint32_t* a,
                                         uint32_t b0, uint32_t b1) {
    asm volatile(
        "mma.sync.aligned.m16n8k16.row.col.f32.bf16.bf16.f32 "
        "{%0,%1,%2,%3}, {%4,%5,%6,%7}, {%8,%9}, {%0,%1,%2,%3};"
        : "+f"(d[0]), "+f"(d[1]), "+f"(d[2]), "+f"(d[3])
        : "r"(a[0]), "r"(a[1]), "r"(a[2]), "r"(a[3]), "r"(b0), "r"(b1));
}
// split two fp32 into packed bf16x2 hi + residual-lo (lower half = v0)
__device__ __forceinline__ void split_pack(float v0, float v1,
                                           uint32_t& hi, uint32_t& lo) {
    __nv_bfloat16 h0 = __float2bfloat16(v0), h1 = __float2bfloat16(v1);
    hi = ((uint32_t)__bfloat16_as_ushort(h1) << 16) | __bfloat16_as_ushort(h0);
    __nv_bfloat16 l0 = __float2bfloat16(v0 - __bfloat162float(h0));
    __nv_bfloat16 l1 = __float2bfloat16(v1 - __bfloat162float(h1));
    lo = ((uint32_t)__bfloat16_as_ushort(l1) << 16) | __bfloat16_as_ushort(l0);
}

// ---------------------------------------------------------------------------
// fp32 -> bf16 hi/lo split (x only)
// ---------------------------------------------------------------------------
__global__ __launch_bounds__(256) void split_kernel(
    const float* __restrict__ in, __nv_bfloat16* __restrict__ hi,
    __nv_bfloat16* __restrict__ lo, int n4)
{
    int idx = blockIdx.x * 256 + threadIdx.x;
    if (idx >= n4) return;
    float4 v = *(const float4*)(in + (size_t)idx * 4);
    uint32_t h0, l0, h1, l1;
    split_pack(v.x, v.y, h0, l0);
    split_pack(v.z, v.w, h1, l1);
    ((uint32_t*)hi)[idx * 2 + 0] = h0;
    ((uint32_t*)hi)[idx * 2 + 1] = h1;
    ((uint32_t*)lo)[idx * 2 + 0] = l0;
    ((uint32_t*)lo)[idx * 2 + 1] = l1;
}

// Transpose + split: W[K,N] fp32 -> T[N,K] bf16 hi/lo
__global__ __launch_bounds__(256) void wsplit_kernel(
    const float* __restrict__ W, __nv_bfloat16* __restrict__ Thi,
    __nv_bfloat16* __restrict__ Tlo, int Krows, int Ncols)
{
    __shared__ float s[32][33];
    const int n0 = blockIdx.x * 32, k0 = blockIdx.y * 32;
    const int tx = threadIdx.x & 31, ty = threadIdx.x >> 5;  // 32x8
#pragma unroll
    for (int i = 0; i < 4; i++) {
        int k = k0 + ty + i * 8;
        s[ty + i * 8][tx] = W[(size_t)k * Ncols + n0 + tx];
    }
    __syncthreads();
#pragma unroll
    for (int i = 0; i < 4; i++) {
        int n = n0 + ty + i * 8;
        float v = s[tx][ty + i * 8];
        __nv_bfloat16 h = __float2bfloat16(v);
        Thi[(size_t)n * Krows + k0 + tx] = h;
        Tlo[(size_t)n * Krows + k0 + tx] =
            __float2bfloat16(v - __bfloat162float(h));
    }
}

// ---------------------------------------------------------------------------
// HMMA GEMM: D[128,128] per CTA = A[m0:,K] * Bt[n0:,K]^T, K=1024, bf16 split.
// 8 warps (2x4), warp tile 64x32. 2-stage cp.async pipeline, swizzled smem.
// MODE 0: emit q/k/v bf16 hi/lo (+bias, q scale). MODE 1: bias + fp32 out.
// ---------------------------------------------------------------------------
#define STG_BYTES 65536   // 4 operands x 16KB
template <int MODE>
__global__ __launch_bounds__(256) void gemm_mma_kernel(
    const __nv_bfloat16* __restrict__ Ahi, const __nv_bfloat16* __restrict__ Alo,
    const __nv_bfloat16* __restrict__ Bhi, const __nv_bfloat16* __restrict__ Blo,
    const float* __restrict__ bias, float* __restrict__ out)
{
    extern __shared__ char smem[];
    const uint32_t smem_u = smem_to_u32(smem);
    const int tid = threadIdx.x;
    const int lane = tid & 31;
    const int warp = tid >> 5;
    const int wm = warp >> 2;          // 0..1
    const int wn = warp & 3;           // 0..3
    const int m0 = blockIdx.y * 128;
    const int n0 = blockIdx.x * 128;

    int lrow[4], lso[4];
#pragma unroll
    for (int i = 0; i < 4; i++) {
        const int c = tid + i * 256;
        const int row = c >> 3, col = c & 7;
        lrow[i] = row;
        lso[i] = row * 128 + ((col ^ (row & 7)) * 16);
    }

    float acc[4][4][4];
#pragma unroll
    for (int i = 0; i < 4; i++)
#pragma unroll
        for (int j = 0; j < 4; j++)
#pragma unroll
            for (int q = 0; q < 4; q++) acc[i][j][q] = 0.0f;

    {
        const uint32_t sb = smem_u;
#pragma unroll
        for (int i = 0; i < 4; i++) {
            const int col = (tid + i * 256) & 7;
            const size_t ga = (size_t)(m0 + lrow[i]) * 1024 + col * 8;
            const size_t gb = (size_t)(n0 + lrow[i]) * 1024 + col * 8;
            CP_ASYNC16(sb + lso[i],          Ahi + ga);
            CP_ASYNC16(sb + 16384 + lso[i],  Alo + ga);
            CP_ASYNC16(sb + 32768 + lso[i],  Bhi + gb);
            CP_ASYNC16(sb + 49152 + lso[i],  Blo + gb);
        }
        CP_COMMIT();
    }

    for (int c = 0; c < 16; ++c) {
        CP_WAIT0();
        __syncthreads();
        if (c + 1 < 16) {
            const int k0 = (c + 1) * 64;
            const uint32_t sb = smem_u + ((c + 1) & 1) * STG_BYTES;
#pragma unroll
            for (int i = 0; i < 4; i++) {
                const int col = (tid + i * 256) & 7;
                const size_t ga = (size_t)(m0 + lrow[i]) * 1024 + k0 + col * 8;
                const size_t gb = (size_t)(n0 + lrow[i]) * 1024 + k0 + col * 8;
                CP_ASYNC16(sb + lso[i],          Ahi + ga);
                CP_ASYNC16(sb + 16384 + lso[i],  Alo + ga);
                CP_ASYNC16(sb + 32768 + lso[i],  Bhi + gb);
                CP_ASYNC16(sb + 49152 + lso[i],  Blo + gb);
            }
            CP_COMMIT();
        }

        const uint32_t sA  = smem_u + (c & 1) * STG_BYTES;
        const uint32_t sAl = sA + 16384;
        const uint32_t sBh = sA + 32768;
        const uint32_t sBl = sA + 49152;

#pragma unroll
        for (int ks = 0; ks < 4; ks++) {
            uint32_t ahi[4][4], alo[4][4];
#pragma unroll
            for (int i = 0; i < 4; i++) {
                const int r = wm * 64 + i * 16 + (lane & 15);
                const int ch = ks * 2 + (lane >> 4);
                const uint32_t off = r * 128 + ((ch ^ (r & 7)) * 16);
                ldsm4(ahi[i], sA + off);
                ldsm4(alo[i], sAl + off);
            }
            uint32_t bhi[2][4], blo[2][4];
#pragma unroll
            for (int jh = 0; jh < 2; jh++) {
                const int r = wn * 32 + jh * 16 + (lane & 15);
                const int ch = ks * 2 + (lane >> 4);
                const uint32_t off = r * 128 + ((ch ^ (r & 7)) * 16);
                ldsm4(bhi[jh], sBh + off);
                ldsm4(blo[jh], sBl + off);
            }
#pragma unroll
            for (int i = 0; i < 4; i++) {
#pragma unroll
                for (int j = 0; j < 4; j++) {
                    const int jh = j >> 1, sel = j & 1;
                    mma16816(acc[i][j], ahi[i], bhi[jh][sel], bhi[jh][sel + 2]);
                    mma16816(acc[i][j], ahi[i], blo[jh][sel], blo[jh][sel + 2]);
                    mma16816(acc[i][j], alo[i], bhi[jh][sel], bhi[jh][sel + 2]);
                }
            }
        }
        __syncthreads();
    }

    // ---- epilogue ----
    const int mrow0 = m0 + wm * 64 + (lane >> 2);
    const int ncol0 = n0 + wn * 32 + (lane & 3) * 2;
#pragma unroll
    for (int i = 0; i < 4; i++) {
#pragma unroll
        for (int j = 0; j < 4; j++) {
            const int n = ncol0 + j * 8;
            const float b0 = bias[n], b1 = bias[n + 1];
#pragma unroll
            for (int half = 0; half < 2; half++) {
                const int m = mrow0 + i * 16 + half * 8;
                const float v0 = acc[i][j][half * 2 + 0] + b0;
                const float v1 = acc[i][j][half * 2 + 1] + b1;
                if (MODE == 0) {
                    const int seg = n >> 10;
                    const float scale = (seg == 0) ? 0.125f : 1.0f;
                    __nv_bfloat16* dhi = (seg == 0) ? g_qhi : (seg == 1) ? g_khi : g_vhi;
                    __nv_bfloat16* dlo = (seg == 0) ? g_qlo : (seg == 1) ? g_klo : g_vlo;
                    const int h = (n & 1023) >> 6;
                    const int b = m >> 11, t = m & 2047;
                    const size_t idx = ((size_t)(b * Hn + h) * Tn + t) * Dn + (n & 63);
                    uint32_t phi, plo;
                    split_pack(v0 * scale, v1 * scale, phi, plo);
                    *(uint32_t*)(dhi + idx) = phi;
                    *(uint32_t*)(dlo + idx) = plo;
                } else {
                    *(float2*)(out + (size_t)m * 1024 + n) =
                        make_float2(v0, v1);
                }
            }
        }
    }
}

// ---------------------------------------------------------------------------
// HMMA flash attention. CTA = 128 q-rows; 8 warps, warp = 16 q-rows x 64 keys.
// K/V tiles 64 keys, bf16 hi/lo, double-buffered cp.async. Online softmax in
// fp32 C-frags; P repacked in registers (C-frag layout == A-frag layout).
// V via ldmatrix.trans. Output written as bf16 hi/lo (g_yhi/g_ylo).
// smem: Qhi 16K | Qlo 16K | 2 x (Khi 8K | Klo 8K | Vhi 8K | Vlo 8K) = 96K.
// ---------------------------------------------------------------------------
#define ATTN_SMEM (32768 + 2*32768)

__global__ __launch_bounds__(256) void attn_mma_kernel()
{
    extern __shared__ char smem[];
    const uint32_t su = smem_to_u32(smem);
    const int tid = threadIdx.x;
    const int lane = tid & 31;
    const int warp = tid >> 5;
    const int qi = (int)gridDim.x - 1 - (int)blockIdx.x;  // big tiles first
    const int bh = blockIdx.y;
    const int q0 = qi * 128;
    const size_t bhoff = (size_t)bh * Tn * Dn;
    const int ktmax = 2 * qi + 1;

    // ---- prefetch Q (hi/lo) + KV tile 0 ----
#pragma unroll
    for (int i = 0; i < 8; i++) {
        const int u = tid + i * 256;           // 0..2047
        const int sub = u >> 10;               // 0=hi 1=lo
        const int v = u & 1023;
        const int r = v >> 3, ch = v & 7;
        const uint32_t so = su + sub * 16384 + r * 128 + ((ch ^ (r & 7)) * 16);
        const __nv_bfloat16* src = (sub ? g_qlo : g_qhi) + bhoff
                                   + (size_t)(q0 + r) * 64 + ch * 8;
        CP_ASYNC16(so, src);
    }
#pragma unroll
    for (int i = 0; i < 8; i++) {
        const int u = tid + i * 256;           // 0..2047
        const int sub = u >> 9;                // 0 khi,1 klo,2 vhi,3 vlo
        const int v = u & 511;
        const int r = v >> 3, ch = v & 7;
        const uint32_t so = su + 32768 + sub * 8192 + r * 128
                          + ((ch ^ (r & 7)) * 16);
        const __nv_bfloat16* base = (sub == 0) ? g_khi : (sub == 1) ? g_klo
                                  : (sub == 2) ? g_vhi : g_vlo;
        CP_ASYNC16(so, base + bhoff + (size_t)r * 64 + ch * 8);
    }
    CP_COMMIT();

    float of[8][4];
#pragma unroll
    for (int j = 0; j < 8; j++)
#pragma unroll
        for (int q = 0; q < 4; q++) of[j][q] = 0.0f;
    float m0r = -1e30f, m1r = -1e30f, l0 = 0.0f, l1 = 0.0f;

    const int row0 = q0 + warp * 16 + (lane >> 2);
    const int row1 = row0 + 8;

    for (int kt = 0; kt <= ktmax; kt++) {
        CP_WAIT0();
        __syncthreads();
        if (kt < ktmax) {
            const int nb = (kt + 1) & 1;
#pragma unroll
            for (int i = 0; i < 8; i++) {
                const int u = tid + i * 256;
                const int sub = u >> 9;
                const int v = u & 511;
                const int r = v >> 3, ch = v & 7;
                const uint32_t so = su + 32768 + nb * 32768 + sub * 8192
                                  + r * 128 + ((ch ^ (r & 7)) * 16);
                const __nv_bfloat16* base = (sub == 0) ? g_khi : (sub == 1) ? g_klo
                                          : (sub == 2) ? g_vhi : g_vlo;
                CP_ASYNC16(so, base + bhoff
                           + (size_t)((kt + 1) * 64 + r) * 64 + ch * 8);
            }
            CP_COMMIT();
        }

        const uint32_t sb  = su + 32768 + (kt & 1) * 32768;
        const uint32_t sKh = sb, sKl = sb + 8192;
        const uint32_t sVh = sb + 16384, sVl = sb + 24576;

        // ---- S = Q K^T (hi/lo 3-term) ----
        float sfr[8][4];
#pragma unroll
        for (int j = 0; j < 8; j++)
#pragma unroll
            for (int q = 0; q < 4; q++) sfr[j][q] = 0.0f;

#pragma unroll
        for (int dc = 0; dc < 4; dc++) {
            const int qr = warp * 16 + (lane & 15);
            const int qch = dc * 2 + (lane >> 4);
            const uint32_t qoff = qr * 128 + ((qch ^ (qr & 7)) * 16);
            uint32_t qh[4], ql[4];
            ldsm4(qh, su + qoff);
            ldsm4(ql, su + 16384 + qoff);
#pragma unroll
            for (int kn = 0; kn < 4; kn++) {
                const int kr = kn * 16 + (lane & 15);
                const uint32_t koff = kr * 128 + ((qch ^ (kr & 7)) * 16);
                uint32_t kh[4], kl[4];
                ldsm4(kh, sKh + koff);
                ldsm4(kl, sKl + koff);
                mma16816(sfr[2 * kn],     qh, kh[0], kh[2]);
                mma16816(sfr[2 * kn],     qh, kl[0], kl[2]);
                mma16816(sfr[2 * kn],     ql, kh[0], kh[2]);
                mma16816(sfr[2 * kn + 1], qh, kh[1], kh[3]);
                mma16816(sfr[2 * kn + 1], qh, kl[1], kl[3]);
                mma16816(sfr[2 * kn + 1], ql, kh[1], kh[3]);
            }
        }

        // ---- causal mask (last two tiles only) ----
        if (kt >= 2 * qi) {
#pragma unroll
            for (int jb = 0; jb < 8; jb++) {
                const int colb = kt * 64 + jb * 8 + (lane & 3) * 2;
                if (colb     > row0) sfr[jb][0] = -1e30f;
                if (colb + 1 > row0) sfr[jb][1] = -1e30f;
                if (colb     > row1) sfr[jb][2] = -1e30f;
                if (colb + 1 > row1) sfr[jb][3] = -1e30f;
            }
        }

        // ---- online softmax ----
        float mx0 = -1e30f, mx1 = -1e30f;
#pragma unroll
        for (int jb = 0; jb < 8; jb++) {
            mx0 = fmaxf(mx0, fmaxf(sfr[jb][0], sfr[jb][1]));
            mx1 = fmaxf(mx1, fmaxf(sfr[jb][2], sfr[jb][3]));
        }
        mx0 = fmaxf(mx0, __shfl_xor_sync(0xffffffffu, mx0, 1));
        mx0 = fmaxf(mx0, __shfl_xor_sync(0xffffffffu, mx0, 2));
        mx1 = fmaxf(mx1, __shfl_xor_sync(0xffffffffu, mx1, 1));
        mx1 = fmaxf(mx1, __shfl_xor_sync(0xffffffffu, mx1, 2));
        const float mn0 = fmaxf(m0r, mx0), mn1 = fmaxf(m1r, mx1);
        const float a0 = __expf(m0r - mn0), a1 = __expf(m1r - mn1);
        m0r = mn0; m1r = mn1;
        l0 *= a0; l1 *= a1;
#pragma unroll
        for (int jb = 0; jb < 8; jb++) {
            sfr[jb][0] = __expf(sfr[jb][0] - m0r);
            sfr[jb][1] = __expf(sfr[jb][1] - m0r);
            sfr[jb][2] = __expf(sfr[jb][2] - m1r);
            sfr[jb][3] = __expf(sfr[jb][3] - m1r);
            l0 += sfr[jb][0] + sfr[jb][1];
            l1 += sfr[jb][2] + sfr[jb][3];
            of[jb][0] *= a0; of[jb][1] *= a0;
            of[jb][2] *= a1; of[jb][3] *= a1;
        }

        // ---- O += P V (P repacked in regs; V via ldmatrix.trans) ----
#pragma unroll
        for (int kc = 0; kc < 4; kc++) {
            uint32_t pah[4], pal[4];
            split_pack(sfr[2 * kc][0],     sfr[2 * kc][1],     pah[0], pal[0]);
            split_pack(sfr[2 * kc][2],     sfr[2 * kc][3],     pah[1], pal[1]);
            split_pack(sfr[2 * kc + 1][0], sfr[2 * kc + 1][1], pah[2], pal[2]);
            split_pack(sfr[2 * kc + 1][2], sfr[2 * kc + 1][3], pah[3], pal[3]);
            const int vr = kc * 16 + (lane & 15);
#pragma unroll
            for (int jd = 0; jd < 4; jd++) {
                const int vch = jd * 2 + (lane >> 4);
                const uint32_t voff = vr * 128 + ((vch ^ (vr & 7)) * 16);
                uint32_t vh[4], vl[4];
                ldsm4t(vh, sVh + voff);
                ldsm4t(vl, sVl + voff);
                mma16816(of[2 * jd],     pah, vh[0], vh[1]);
                mma16816(of[2 * jd],     pah, vl[0], vl[1]);
                mma16816(of[2 * jd],     pal, vh[0], vh[1]);
                mma16816(of[2 * jd + 1], pah, vh[2], vh[3]);
                mma16816(of[2 * jd + 1], pah, vl[2], vl[3]);
                mma16816(of[2 * jd + 1], pal, vh[2], vh[3]);
            }
        }
    }

    // ---- final normalize + write y as bf16 hi/lo ----
    l0 += __shfl_xor_sync(0xffffffffu, l0, 1);
    l0 += __shfl_xor_sync(0xffffffffu, l0, 2);
    l1 += __shfl_xor_sync(0xffffffffu, l1, 1);
    l1 += __shfl_xor_sync(0xffffffffu, l1, 2);
    const float inv0 = 1.0f / l0, inv1 = 1.0f / l1;

    const int b = bh >> 4, h = bh & 15;
    const int col0 = h * 64 + (lane & 3) * 2;
#pragma unroll
    for (int jd = 0; jd < 8; jd++) {
        uint32_t phi, plo;
        const size_t i0 = (size_t)(b * Tn + row0) * Cn + col0 + jd * 8;
        split_pack(of[jd][0] * inv0, of[jd][1] * inv0, phi, plo);
        *(uint32_t*)(g_yhi + i0) = phi;
        *(uint32_t*)(g_ylo + i0) = plo;
        const size_t i1 = (size_t)(b * Tn + row1) * Cn + col0 + jd * 8;
        split_pack(of[jd][2] * inv1, of[jd][3] * inv1, phi, plo);
        *(uint32_t*)(g_yhi + i1) = phi;
        *(uint32_t*)(g_ylo + i1) = plo;
    }
}

// ---------------------------------------------------------------------------
extern "C" void kernel_launch(void* const* d_in, const int* in_sizes, int n_in,
                              void* d_out, int out_size)
{
    const float* x      = (const float*)d_in[0];
    const float* W_attn = (const float*)d_in[1];
    const float* b_attn = (const float*)d_in[2];
    const float* W_proj = (const float*)d_in[3];
    const float* b_proj = (const float*)d_in[4];
    float* out = (float*)d_out;

    __nv_bfloat16 *xhi, *xlo, *yhi, *ylo, *wahi, *walo, *wphi, *wplo;
    cudaGetSymbolAddress((void**)&xhi,  g_xhi);
    cudaGetSymbolAddress((void**)&xlo,  g_xlo);
    cudaGetSymbolAddress((void**)&yhi,  g_yhi);
    cudaGetSymbolAddress((void**)&ylo,  g_ylo);
    cudaGetSymbolAddress((void**)&wahi, g_wahi);
    cudaGetSymbolAddress((void**)&walo, g_walo);
    cudaGetSymbolAddress((void**)&wphi, g_wphi);
    cudaGetSymbolAddress((void**)&wplo, g_wplo);

    const int gemm_smem = 2 * STG_BYTES;  // 131072 B
    cudaFuncSetAttribute(gemm_mma_kernel<0>,
                         cudaFuncAttributeMaxDynamicSharedMemorySize, gemm_smem);
    cudaFuncSetAttribute(gemm_mma_kernel<1>,
                         cudaFuncAttributeMaxDynamicSharedMemorySize, gemm_smem);
    cudaFuncSetAttribute(attn_mma_kernel,
                         cudaFuncAttributeMaxDynamicSharedMemorySize, ATTN_SMEM);

    // 1) splits
    split_kernel<<<NTOK * Cn / 4 / 256, 256>>>(x, xhi, xlo, NTOK * Cn / 4);
    wsplit_kernel<<<dim3(3 * Cn / 32, Cn / 32), 256>>>(W_attn, wahi, walo, Cn, 3 * Cn);
    wsplit_kernel<<<dim3(Cn / 32, Cn / 32), 256>>>(W_proj, wphi, wplo, Cn, Cn);

    // 2) qkv = x @ W_attn + b  -> q/k/v bf16 hi/lo
    gemm_mma_kernel<0><<<dim3(24, 64), 256, gemm_smem>>>(
        xhi, xlo, wahi, walo, b_attn, nullptr);

    // 3) HMMA flash attention -> yhi/ylo
    attn_mma_kernel<<<dim3(Tn / 128, Bsz * Hn), 256, ATTN_SMEM>>>();

    // 4) proj GEMM -> out
    gemm_mma_kernel<1><<<dim3(8, 64), 256, gemm_smem>>>(
        yhi, ylo, wphi, wplo, b_proj, out);
}

// round 7
// speedup vs baseline: 2.6025x; 1.0025x over previous
#include <cuda_runtime.h>
#include <cuda_bf16.h>
#include <cstdint>

#define Bsz 4
#define Tn 2048
#define Cn 1024
#define Hn 16
#define Dn 64
#define NTOK (Bsz*Tn)   // 8192

// ---------------------------------------------------------------------------
// Scratch (device globals: allocation-free)
// ---------------------------------------------------------------------------
__device__ __align__(16) __nv_bfloat16 g_xhi[NTOK*Cn];
__device__ __align__(16) __nv_bfloat16 g_xlo[NTOK*Cn];
__device__ __align__(16) __nv_bfloat16 g_yhi[NTOK*Cn];
__device__ __align__(16) __nv_bfloat16 g_ylo[NTOK*Cn];
__device__ __align__(16) __nv_bfloat16 g_wahi[3*Cn*Cn];   // W_attn^T [3072][1024]
__device__ __align__(16) __nv_bfloat16 g_walo[3*Cn*Cn];
__device__ __align__(16) __nv_bfloat16 g_wphi[Cn*Cn];     // W_proj^T [1024][1024]
__device__ __align__(16) __nv_bfloat16 g_wplo[Cn*Cn];
// q/k/v as bf16 hi/lo, layout [B,H,T,D]
__device__ __align__(16) __nv_bfloat16 g_qhi[Bsz*Hn*Tn*Dn];
__device__ __align__(16) __nv_bfloat16 g_qlo[Bsz*Hn*Tn*Dn];
__device__ __align__(16) __nv_bfloat16 g_khi[Bsz*Hn*Tn*Dn];
__device__ __align__(16) __nv_bfloat16 g_klo[Bsz*Hn*Tn*Dn];
__device__ __align__(16) __nv_bfloat16 g_vhi[Bsz*Hn*Tn*Dn];
__device__ __align__(16) __nv_bfloat16 g_vlo[Bsz*Hn*Tn*Dn];

// ---------------------------------------------------------------------------
// Baseline-PTX helpers (sm_80-level; compile for plain sm_103 target)
// ---------------------------------------------------------------------------
__device__ __forceinline__ uint32_t smem_to_u32(const void* p) {
    uint32_t a;
    asm("{ .reg .u64 t; cvta.to.shared.u64 t, %1; cvt.u32.u64 %0, t; }"
        : "=r"(a) : "l"(p));
    return a;
}
#define CP_ASYNC16(dst_u32, src_ptr) \
    asm volatile("cp.async.cg.shared.global [%0], [%1], 16;" \
        :: "r"(dst_u32), "l"(src_ptr))
#define CP_COMMIT() asm volatile("cp.async.commit_group;" ::: "memory")
#define CP_WAIT0()  asm volatile("cp.async.wait_group 0;" ::: "memory")

__device__ __forceinline__ void ldsm4(uint32_t* r, uint32_t addr) {
    asm volatile("ldmatrix.sync.aligned.m8n8.x4.shared.b16 {%0,%1,%2,%3}, [%4];"
        : "=r"(r[0]), "=r"(r[1]), "=r"(r[2]), "=r"(r[3]) : "r"(addr));
}
__device__ __forceinline__ void ldsm4t(uint32_t* r, uint32_t addr) {
    asm volatile("ldmatrix.sync.aligned.m8n8.x4.trans.shared.b16 {%0,%1,%2,%3}, [%4];"
        : "=r"(r[0]), "=r"(r[1]), "=r"(r[2]), "=r"(r[3]) : "r"(addr));
}
__device__ __forceinline__ void mma16816(float* d, const uint32_t* a,
                                         uint32_t b0, uint32_t b1) {
    asm volatile(
        "mma.sync.aligned.m16n8k16.row.col.f32.bf16.bf16.f32 "
        "{%0,%1,%2,%3}, {%4,%5,%6,%7}, {%8,%9}, {%0,%1,%2,%3};"
        : "+f"(d[0]), "+f"(d[1]), "+f"(d[2]), "+f"(d[3])
        : "r"(a[0]), "r"(a[1]), "r"(a[2]), "r"(a[3]), "r"(b0), "r"(b1));
}
// split two fp32 into packed bf16x2 hi + residual-lo (lower half = v0)
__device__ __forceinline__ void split_pack(float v0, float v1,
                                           uint32_t& hi, uint32_t& lo) {
    __nv_bfloat16 h0 = __float2bfloat16(v0), h1 = __float2bfloat16(v1);
    hi = ((uint32_t)__bfloat16_as_ushort(h1) << 16) | __bfloat16_as_ushort(h0);
    __nv_bfloat16 l0 = __float2bfloat16(v0 - __bfloat162float(h0));
    __nv_bfloat16 l1 = __float2bfloat16(v1 - __bfloat162float(h1));
    lo = ((uint32_t)__bfloat16_as_ushort(l1) << 16) | __bfloat16_as_ushort(l0);
}

// ---------------------------------------------------------------------------
// fp32 -> bf16 hi/lo split (x only)
// ---------------------------------------------------------------------------
__global__ __launch_bounds__(256) void split_kernel(
    const float* __restrict__ in, __nv_bfloat16* __restrict__ hi,
    __nv_bfloat16* __restrict__ lo, int n4)
{
    int idx = blockIdx.x * 256 + threadIdx.x;
    if (idx >= n4) return;
    float4 v = *(const float4*)(in + (size_t)idx * 4);
    uint32_t h0, l0, h1, l1;
    split_pack(v.x, v.y, h0, l0);
    split_pack(v.z, v.w, h1, l1);
    ((uint32_t*)hi)[idx * 2 + 0] = h0;
    ((uint32_t*)hi)[idx * 2 + 1] = h1;
    ((uint32_t*)lo)[idx * 2 + 0] = l0;
    ((uint32_t*)lo)[idx * 2 + 1] = l1;
}

// Transpose + split: W[K,N] fp32 -> T[N,K] bf16 hi/lo
__global__ __launch_bounds__(256) void wsplit_kernel(
    const float* __restrict__ W, __nv_bfloat16* __restrict__ Thi,
    __nv_bfloat16* __restrict__ Tlo, int Krows, int Ncols)
{
    __shared__ float s[32][33];
    const int n0 = blockIdx.x * 32, k0 = blockIdx.y * 32;
    const int tx = threadIdx.x & 31, ty = threadIdx.x >> 5;  // 32x8
#pragma unroll
    for (int i = 0; i < 4; i++) {
        int k = k0 + ty + i * 8;
        s[ty + i * 8][tx] = W[(size_t)k * Ncols + n0 + tx];
    }
    __syncthreads();
#pragma unroll
    for (int i = 0; i < 4; i++) {
        int n = n0 + ty + i * 8;
        float v = s[tx][ty + i * 8];
        __nv_bfloat16 h = __float2bfloat16(v);
        Thi[(size_t)n * Krows + k0 + tx] = h;
        Tlo[(size_t)n * Krows + k0 + tx] =
            __float2bfloat16(v - __bfloat162float(h));
    }
}

// ---------------------------------------------------------------------------
// HMMA GEMM: D[128,128] per CTA = A[m0:,K] * Bt[n0:,K]^T, K=1024, bf16 split.
// 8 warps (2x4), warp tile 64x32. 2-stage cp.async pipeline, swizzled smem.
// MODE 0: emit q/k/v bf16 hi/lo (+bias, q scale). MODE 1: bias + fp32 out.
// ---------------------------------------------------------------------------
#define STG_BYTES 65536   // 4 operands x 16KB
template <int MODE>
__global__ __launch_bounds__(256) void gemm_mma_kernel(
    const __nv_bfloat16* __restrict__ Ahi, const __nv_bfloat16* __restrict__ Alo,
    const __nv_bfloat16* __restrict__ Bhi, const __nv_bfloat16* __restrict__ Blo,
    const float* __restrict__ bias, float* __restrict__ out)
{
    extern __shared__ char smem[];
    const uint32_t smem_u = smem_to_u32(smem);
    const int tid = threadIdx.x;
    const int lane = tid & 31;
    const int warp = tid >> 5;
    const int wm = warp >> 2;          // 0..1
    const int wn = warp & 3;           // 0..3
    const int m0 = blockIdx.y * 128;
    const int n0 = blockIdx.x * 128;

    int lrow[4], lso[4];
#pragma unroll
    for (int i = 0; i < 4; i++) {
        const int c = tid + i * 256;
        const int row = c >> 3, col = c & 7;
        lrow[i] = row;
        lso[i] = row * 128 + ((col ^ (row & 7)) * 16);
    }

    float acc[4][4][4];
#pragma unroll
    for (int i = 0; i < 4; i++)
#pragma unroll
        for (int j = 0; j < 4; j++)
#pragma unroll
            for (int q = 0; q < 4; q++) acc[i][j][q] = 0.0f;

    {
        const uint32_t sb = smem_u;
#pragma unroll
        for (int i = 0; i < 4; i++) {
            const int col = (tid + i * 256) & 7;
            const size_t ga = (size_t)(m0 + lrow[i]) * 1024 + col * 8;
            const size_t gb = (size_t)(n0 + lrow[i]) * 1024 + col * 8;
            CP_ASYNC16(sb + lso[i],          Ahi + ga);
            CP_ASYNC16(sb + 16384 + lso[i],  Alo + ga);
            CP_ASYNC16(sb + 32768 + lso[i],  Bhi + gb);
            CP_ASYNC16(sb + 49152 + lso[i],  Blo + gb);
        }
        CP_COMMIT();
    }

    for (int c = 0; c < 16; ++c) {
        CP_WAIT0();
        __syncthreads();
        if (c + 1 < 16) {
            const int k0 = (c + 1) * 64;
            const uint32_t sb = smem_u + ((c + 1) & 1) * STG_BYTES;
#pragma unroll
            for (int i = 0; i < 4; i++) {
                const int col = (tid + i * 256) & 7;
                const size_t ga = (size_t)(m0 + lrow[i]) * 1024 + k0 + col * 8;
                const size_t gb = (size_t)(n0 + lrow[i]) * 1024 + k0 + col * 8;
                CP_ASYNC16(sb + lso[i],          Ahi + ga);
                CP_ASYNC16(sb + 16384 + lso[i],  Alo + ga);
                CP_ASYNC16(sb + 32768 + lso[i],  Bhi + gb);
                CP_ASYNC16(sb + 49152 + lso[i],  Blo + gb);
            }
            CP_COMMIT();
        }

        const uint32_t sA  = smem_u + (c & 1) * STG_BYTES;
        const uint32_t sAl = sA + 16384;
        const uint32_t sBh = sA + 32768;
        const uint32_t sBl = sA + 49152;

#pragma unroll
        for (int ks = 0; ks < 4; ks++) {
            uint32_t ahi[4][4], alo[4][4];
#pragma unroll
            for (int i = 0; i < 4; i++) {
                const int r = wm * 64 + i * 16 + (lane & 15);
                const int ch = ks * 2 + (lane >> 4);
                const uint32_t off = r * 128 + ((ch ^ (r & 7)) * 16);
                ldsm4(ahi[i], sA + off);
                ldsm4(alo[i], sAl + off);
            }
            uint32_t bhi[2][4], blo[2][4];
#pragma unroll
            for (int jh = 0; jh < 2; jh++) {
                const int r = wn * 32 + jh * 16 + (lane & 15);
                const int ch = ks * 2 + (lane >> 4);
                const uint32_t off = r * 128 + ((ch ^ (r & 7)) * 16);
                ldsm4(bhi[jh], sBh + off);
                ldsm4(blo[jh], sBl + off);
            }
#pragma unroll
            for (int i = 0; i < 4; i++) {
#pragma unroll
                for (int j = 0; j < 4; j++) {
                    const int jh = j >> 1, sel = j & 1;
                    mma16816(acc[i][j], ahi[i], bhi[jh][sel], bhi[jh][sel + 2]);
                    mma16816(acc[i][j], ahi[i], blo[jh][sel], blo[jh][sel + 2]);
                    mma16816(acc[i][j], alo[i], bhi[jh][sel], bhi[jh][sel + 2]);
                }
            }
        }
        __syncthreads();
    }

    // ---- epilogue ----
    const int mrow0 = m0 + wm * 64 + (lane >> 2);
    const int ncol0 = n0 + wn * 32 + (lane & 3) * 2;
#pragma unroll
    for (int i = 0; i < 4; i++) {
#pragma unroll
        for (int j = 0; j < 4; j++) {
            const int n = ncol0 + j * 8;
            const float b0 = bias[n], b1 = bias[n + 1];
#pragma unroll
            for (int half = 0; half < 2; half++) {
                const int m = mrow0 + i * 16 + half * 8;
                const float v0 = acc[i][j][half * 2 + 0] + b0;
                const float v1 = acc[i][j][half * 2 + 1] + b1;
                if (MODE == 0) {
                    const int seg = n >> 10;
                    const float scale = (seg == 0) ? 0.125f : 1.0f;
                    __nv_bfloat16* dhi = (seg == 0) ? g_qhi : (seg == 1) ? g_khi : g_vhi;
                    __nv_bfloat16* dlo = (seg == 0) ? g_qlo : (seg == 1) ? g_klo : g_vlo;
                    const int h = (n & 1023) >> 6;
                    const int b = m >> 11, t = m & 2047;
                    const size_t idx = ((size_t)(b * Hn + h) * Tn + t) * Dn + (n & 63);
                    uint32_t phi, plo;
                    split_pack(v0 * scale, v1 * scale, phi, plo);
                    *(uint32_t*)(dhi + idx) = phi;
                    *(uint32_t*)(dlo + idx) = plo;
                } else {
                    *(float2*)(out + (size_t)m * 1024 + n) =
                        make_float2(v0, v1);
                }
            }
        }
    }
}

// ---------------------------------------------------------------------------
// HMMA flash attention. CTA = 128 q-rows; 8 warps, warp = 16 q-rows x 64 keys.
// K/V tiles 64 keys, bf16 hi/lo, double-buffered cp.async. Online softmax in
// fp32 C-frags; P repacked in registers (C-frag layout == A-frag layout).
// V via ldmatrix.trans. Output written as bf16 hi/lo (g_yhi/g_ylo).
// smem: Qhi 16K | Qlo 16K | 2 x (Khi 8K | Klo 8K | Vhi 8K | Vlo 8K) = 96K.
// ---------------------------------------------------------------------------
#define ATTN_SMEM (32768 + 2*32768)

__global__ __launch_bounds__(256) void attn_mma_kernel()
{
    extern __shared__ char smem[];
    const uint32_t su = smem_to_u32(smem);
    const int tid = threadIdx.x;
    const int lane = tid & 31;
    const int warp = tid >> 5;
    const int qi = (int)gridDim.x - 1 - (int)blockIdx.x;  // big tiles first
    const int bh = blockIdx.y;
    const int q0 = qi * 128;
    const size_t bhoff = (size_t)bh * Tn * Dn;
    const int ktmax = 2 * qi + 1;

    // ---- prefetch Q (hi/lo) + KV tile 0 ----
#pragma unroll
    for (int i = 0; i < 8; i++) {
        const int u = tid + i * 256;           // 0..2047
        const int sub = u >> 10;               // 0=hi 1=lo
        const int v = u & 1023;
        const int r = v >> 3, ch = v & 7;
        const uint32_t so = su + sub * 16384 + r * 128 + ((ch ^ (r & 7)) * 16);
        const __nv_bfloat16* src = (sub ? g_qlo : g_qhi) + bhoff
                                   + (size_t)(q0 + r) * 64 + ch * 8;
        CP_ASYNC16(so, src);
    }
#pragma unroll
    for (int i = 0; i < 8; i++) {
        const int u = tid + i * 256;           // 0..2047
        const int sub = u >> 9;                // 0 khi,1 klo,2 vhi,3 vlo
        const int v = u & 511;
        const int r = v >> 3, ch = v & 7;
        const uint32_t so = su + 32768 + sub * 8192 + r * 128
                          + ((ch ^ (r & 7)) * 16);
        const __nv_bfloat16* base = (sub == 0) ? g_khi : (sub == 1) ? g_klo
                                  : (sub == 2) ? g_vhi : g_vlo;
        CP_ASYNC16(so, base + bhoff + (size_t)r * 64 + ch * 8);
    }
    CP_COMMIT();

    float of[8][4];
#pragma unroll
    for (int j = 0; j < 8; j++)
#pragma unroll
        for (int q = 0; q < 4; q++) of[j][q] = 0.0f;
    float m0r = -1e30f, m1r = -1e30f, l0 = 0.0f, l1 = 0.0f;

    const int row0 = q0 + warp * 16 + (lane >> 2);
    const int row1 = row0 + 8;

    for (int kt = 0; kt <= ktmax; kt++) {
        CP_WAIT0();
        __syncthreads();
        if (kt < ktmax) {
            const int nb = (kt + 1) & 1;
#pragma unroll
            for (int i = 0; i < 8; i++) {
                const int u = tid + i * 256;
                const int sub = u >> 9;
                const int v = u & 511;
                const int r = v >> 3, ch = v & 7;
                const uint32_t so = su + 32768 + nb * 32768 + sub * 8192
                                  + r * 128 + ((ch ^ (r & 7)) * 16);
                const __nv_bfloat16* base = (sub == 0) ? g_khi : (sub == 1) ? g_klo
                                          : (sub == 2) ? g_vhi : g_vlo;
                CP_ASYNC16(so, base + bhoff
                           + (size_t)((kt + 1) * 64 + r) * 64 + ch * 8);
            }
            CP_COMMIT();
        }

        const uint32_t sb  = su + 32768 + (kt & 1) * 32768;
        const uint32_t sKh = sb, sKl = sb + 8192;
        const uint32_t sVh = sb + 16384, sVl = sb + 24576;

        // ---- S = Q K^T (hi/lo 3-term) ----
        float sfr[8][4];
#pragma unroll
        for (int j = 0; j < 8; j++)
#pragma unroll
            for (int q = 0; q < 4; q++) sfr[j][q] = 0.0f;

#pragma unroll
        for (int dc = 0; dc < 4; dc++) {
            const int qr = warp * 16 + (lane & 15);
            const int qch = dc * 2 + (lane >> 4);
            const uint32_t qoff = qr * 128 + ((qch ^ (qr & 7)) * 16);
            uint32_t qh[4], ql[4];
            ldsm4(qh, su + qoff);
            ldsm4(ql, su + 16384 + qoff);
#pragma unroll
            for (int kn = 0; kn < 4; kn++) {
                const int kr = kn * 16 + (lane & 15);
                const uint32_t koff = kr * 128 + ((qch ^ (kr & 7)) * 16);
                uint32_t kh[4], kl[4];
                ldsm4(kh, sKh + koff);
                ldsm4(kl, sKl + koff);
                mma16816(sfr[2 * kn],     qh, kh[0], kh[2]);
                mma16816(sfr[2 * kn],     qh, kl[0], kl[2]);
                mma16816(sfr[2 * kn],     ql, kh[0], kh[2]);
                mma16816(sfr[2 * kn + 1], qh, kh[1], kh[3]);
                mma16816(sfr[2 * kn + 1], qh, kl[1], kl[3]);
                mma16816(sfr[2 * kn + 1], ql, kh[1], kh[3]);
            }
        }

        // ---- causal mask (last two tiles only) ----
        if (kt >= 2 * qi) {
#pragma unroll
            for (int jb = 0; jb < 8; jb++) {
                const int colb = kt * 64 + jb * 8 + (lane & 3) * 2;
                if (colb     > row0) sfr[jb][0] = -1e30f;
                if (colb + 1 > row0) sfr[jb][1] = -1e30f;
                if (colb     > row1) sfr[jb][2] = -1e30f;
                if (colb + 1 > row1) sfr[jb][3] = -1e30f;
            }
        }

        // ---- online softmax ----
        float mx0 = -1e30f, mx1 = -1e30f;
#pragma unroll
        for (int jb = 0; jb < 8; jb++) {
            mx0 = fmaxf(mx0, fmaxf(sfr[jb][0], sfr[jb][1]));
            mx1 = fmaxf(mx1, fmaxf(sfr[jb][2], sfr[jb][3]));
        }
        mx0 = fmaxf(mx0, __shfl_xor_sync(0xffffffffu, mx0, 1));
        mx0 = fmaxf(mx0, __shfl_xor_sync(0xffffffffu, mx0, 2));
        mx1 = fmaxf(mx1, __shfl_xor_sync(0xffffffffu, mx1, 1));
        mx1 = fmaxf(mx1, __shfl_xor_sync(0xffffffffu, mx1, 2));
        const float mn0 = fmaxf(m0r, mx0), mn1 = fmaxf(m1r, mx1);
        const float a0 = __expf(m0r - mn0), a1 = __expf(m1r - mn1);
        m0r = mn0; m1r = mn1;
        l0 *= a0; l1 *= a1;
#pragma unroll
        for (int jb = 0; jb < 8; jb++) {
            sfr[jb][0] = __expf(sfr[jb][0] - m0r);
            sfr[jb][1] = __expf(sfr[jb][1] - m0r);
            sfr[jb][2] = __expf(sfr[jb][2] - m1r);
            sfr[jb][3] = __expf(sfr[jb][3] - m1r);
            l0 += sfr[jb][0] + sfr[jb][1];
            l1 += sfr[jb][2] + sfr[jb][3];
            of[jb][0] *= a0; of[jb][1] *= a0;
            of[jb][2] *= a1; of[jb][3] *= a1;
        }

        // ---- O += P V (P repacked in regs; V via ldmatrix.trans) ----
#pragma unroll
        for (int kc = 0; kc < 4; kc++) {
            uint32_t pah[4], pal[4];
            split_pack(sfr[2 * kc][0],     sfr[2 * kc][1],     pah[0], pal[0]);
            split_pack(sfr[2 * kc][2],     sfr[2 * kc][3],     pah[1], pal[1]);
            split_pack(sfr[2 * kc + 1][0], sfr[2 * kc + 1][1], pah[2], pal[2]);
            split_pack(sfr[2 * kc + 1][2], sfr[2 * kc + 1][3], pah[3], pal[3]);
            const int vr = kc * 16 + (lane & 15);
#pragma unroll
            for (int jd = 0; jd < 4; jd++) {
                const int vch = jd * 2 + (lane >> 4);
                const uint32_t voff = vr * 128 + ((vch ^ (vr & 7)) * 16);
                uint32_t vh[4], vl[4];
                ldsm4t(vh, sVh + voff);
                ldsm4t(vl, sVl + voff);
                mma16816(of[2 * jd],     pah, vh[0], vh[1]);
                mma16816(of[2 * jd],     pah, vl[0], vl[1]);
                mma16816(of[2 * jd],     pal, vh[0], vh[1]);
                mma16816(of[2 * jd + 1], pah, vh[2], vh[3]);
                mma16816(of[2 * jd + 1], pah, vl[2], vl[3]);
                mma16816(of[2 * jd + 1], pal, vh[2], vh[3]);
            }
        }
    }

    // ---- final normalize + write y as bf16 hi/lo ----
    l0 += __shfl_xor_sync(0xffffffffu, l0, 1);
    l0 += __shfl_xor_sync(0xffffffffu, l0, 2);
    l1 += __shfl_xor_sync(0xffffffffu, l1, 1);
    l1 += __shfl_xor_sync(0xffffffffu, l1, 2);
    const float inv0 = 1.0f / l0, inv1 = 1.0f / l1;

    const int b = bh >> 4, h = bh & 15;
    const int col0 = h * 64 + (lane & 3) * 2;
#pragma unroll
    for (int jd = 0; jd < 8; jd++) {
        uint32_t phi, plo;
        const size_t i0 = (size_t)(b * Tn + row0) * Cn + col0 + jd * 8;
        split_pack(of[jd][0] * inv0, of[jd][1] * inv0, phi, plo);
        *(uint32_t*)(g_yhi + i0) = phi;
        *(uint32_t*)(g_ylo + i0) = plo;
        const size_t i1 = (size_t)(b * Tn + row1) * Cn + col0 + jd * 8;
        split_pack(of[jd][2] * inv1, of[jd][3] * inv1, phi, plo);
        *(uint32_t*)(g_yhi + i1) = phi;
        *(uint32_t*)(g_ylo + i1) = plo;
    }
}

// ---------------------------------------------------------------------------
extern "C" void kernel_launch(void* const* d_in, const int* in_sizes, int n_in,
                              void* d_out, int out_size)
{
    const float* x      = (const float*)d_in[0];
    const float* W_attn = (const float*)d_in[1];
    const float* b_attn = (const float*)d_in[2];
    const float* W_proj = (const float*)d_in[3];
    const float* b_proj = (const float*)d_in[4];
    float* out = (float*)d_out;

    __nv_bfloat16 *xhi, *xlo, *yhi, *ylo, *wahi, *walo, *wphi, *wplo;
    cudaGetSymbolAddress((void**)&xhi,  g_xhi);
    cudaGetSymbolAddress((void**)&xlo,  g_xlo);
    cudaGetSymbolAddress((void**)&yhi,  g_yhi);
    cudaGetSymbolAddress((void**)&ylo,  g_ylo);
    cudaGetSymbolAddress((void**)&wahi, g_wahi);
    cudaGetSymbolAddress((void**)&walo, g_walo);
    cudaGetSymbolAddress((void**)&wphi, g_wphi);
    cudaGetSymbolAddress((void**)&wplo, g_wplo);

    const int gemm_smem = 2 * STG_BYTES;  // 131072 B
    cudaFuncSetAttribute(gemm_mma_kernel<0>,
                         cudaFuncAttributeMaxDynamicSharedMemorySize, gemm_smem);
    cudaFuncSetAttribute(gemm_mma_kernel<1>,
                         cudaFuncAttributeMaxDynamicSharedMemorySize, gemm_smem);
    cudaFuncSetAttribute(attn_mma_kernel,
                         cudaFuncAttributeMaxDynamicSharedMemorySize, ATTN_SMEM);

    // 1) splits
    split_kernel<<<NTOK * Cn / 4 / 256, 256>>>(x, xhi, xlo, NTOK * Cn / 4);
    wsplit_kernel<<<dim3(3 * Cn / 32, Cn / 32), 256>>>(W_attn, wahi, walo, Cn, 3 * Cn);
    wsplit_kernel<<<dim3(Cn / 32, Cn / 32), 256>>>(W_proj, wphi, wplo, Cn, Cn);

    // 2) qkv = x @ W_attn + b  -> q/k/v bf16 hi/lo
    gemm_mma_kernel<0><<<dim3(24, 64), 256, gemm_smem>>>(
        xhi, xlo, wahi, walo, b_attn, nullptr);

    // 3) HMMA flash attention -> yhi/ylo
    attn_mma_kernel<<<dim3(Tn / 128, Bsz * Hn), 256, ATTN_SMEM>>>();

    // 4) proj GEMM -> out
    gemm_mma_kernel<1><<<dim3(8, 64), 256, gemm_smem>>>(
        yhi, ylo, wphi, wplo, b_proj, out);
}